// round 9
// baseline (speedup 1.0000x reference)
#include <cuda_runtime.h>
#include <cuda_fp16.h>
#include <math.h>
#include <stdint.h>

#define D_MODEL 768
#define VOCAB   32128
#define NTOK    2048
#define NTILES_N 251           // VOCAB / 128
#define BM 128
#define BN 128
#define BKH 64                 // k-halfs per chunk (128 B per row)
#define NCHUNK (D_MODEL / BKH) // 12
#define ASTRH 72               // smem row stride in halfs (144 B, conflict-free)
#define ABYTES (BM * ASTRH * 2)    // 18432
#define BBYTES (BN * ASTRH * 2)    // 18432
#define BUFB   (ABYTES + BBYTES)   // 36864
#define SMEM_TOTAL (3 * BUFB)      // 110592 -> 2 CTAs/SM
#define ESTR 132               // epilogue smem row stride in floats (128r*132*4=67584)

#define WCVT_BLOCKS 6024       // (32128*768/4) float4s / (256*4) = exact

// Scratch (static: no allocations allowed)
__device__ __half g_Hh[(size_t)NTOK * D_MODEL];
__device__ __half g_Wh[(size_t)VOCAB * D_MODEL];
__device__ float  g_pmax[(size_t)NTOK * NTILES_N];
__device__ float  g_psum[(size_t)NTOK * NTILES_N];
__device__ float  g_nll[NTOK];
__device__ float  g_cnt[NTOK];
__device__ unsigned int g_done;   // zero-init; self-resetting per launch

__device__ __forceinline__ uint32_t smem_u32(const void* p) {
    return (uint32_t)__cvta_generic_to_shared(p);
}
__device__ __forceinline__ void cp16(uint32_t dst, const void* src) {
    asm volatile("cp.async.cg.shared.global [%0], [%1], 16;"
                 :: "r"(dst), "l"(src) : "memory");
}
#define CP_COMMIT() asm volatile("cp.async.commit_group;" ::: "memory")
#define CP_WAIT(n)  asm volatile("cp.async.wait_group %0;" :: "n"(n) : "memory")

#define MMA_F16(acc, A0, A1, A2, A3, B0, B1)                                   \
    asm volatile(                                                              \
        "mma.sync.aligned.m16n8k16.row.col.f32.f16.f16.f32 "                   \
        "{%0,%1,%2,%3},{%4,%5,%6,%7},{%8,%9},{%0,%1,%2,%3};\n"                 \
        : "+f"((acc)[0]), "+f"((acc)[1]), "+f"((acc)[2]), "+f"((acc)[3])       \
        : "r"(A0), "r"(A1), "r"(A2), "r"(A3), "r"(B0), "r"(B1))

// ---------------------------------------------------------------------------
// 1) Fused prep (all coalesced).
// ---------------------------------------------------------------------------
__global__ void prep_kernel(const float* __restrict__ x,
                            const float* __restrict__ w,
                            const float* __restrict__ W) {
    const int tid = threadIdx.x;
    if (blockIdx.x < NTOK) {
        const int row = blockIdx.x;
        const float* xr = x + (size_t)row * D_MODEL;
        float ssq = 0.f;
        #pragma unroll
        for (int i = 0; i < 3; ++i) { float v = xr[tid + i * 256]; ssq += v * v; }
        __shared__ float red[256];
        red[tid] = ssq; __syncthreads();
        #pragma unroll
        for (int s = 128; s > 0; s >>= 1) {
            if (tid < s) red[tid] += red[tid + s];
            __syncthreads();
        }
        const float inv = rsqrtf(red[0] * (1.0f / D_MODEL) + 1e-6f);
        #pragma unroll
        for (int i = 0; i < 3; ++i) {
            const int k = tid + i * 256;
            g_Hh[(size_t)row * D_MODEL + k] = __float2half_rn(xr[k] * inv * w[k]);
        }
    } else {
        const size_t nf4 = (size_t)VOCAB * D_MODEL / 4;       // 6168576
        const float4* src = (const float4*)W;
        const size_t t0 = (size_t)(blockIdx.x - NTOK) * 256 + tid;
        #pragma unroll
        for (int i = 0; i < 4; ++i) {
            const size_t idx = t0 + (size_t)i * WCVT_BLOCKS * 256;
            if (idx < nf4) {
                const float4 v = src[idx];
                __half2* d = (__half2*)(g_Wh + idx * 4);
                d[0] = __floats2half2_rn(v.x, v.y);
                d[1] = __floats2half2_rn(v.z, v.w);
            }
        }
    }
}

// ---------------------------------------------------------------------------
// 2) GEMM (mma.sync f16 m16n8k16) 128x128 tile, cp.async 3-stage, 2 CTAs/SM,
//    smem-transposed coalesced epilogue + fused lse partials.
// ---------------------------------------------------------------------------
__device__ __forceinline__ void stage_chunk(uint32_t sbuf, int kt,
                                            size_t bm, size_t bn, int tid) {
    const int row = tid >> 3;          // 0..31
    const int c16 = tid & 7;
    #pragma unroll
    for (int i = 0; i < 4; ++i) {      // A: 128 rows
        const int r = row + i * 32;
        cp16(sbuf + (uint32_t)(r * (ASTRH * 2) + c16 * 16),
             g_Hh + (bm + r) * D_MODEL + kt * BKH + c16 * 8);
    }
    #pragma unroll
    for (int i = 0; i < 4; ++i) {      // B: 128 rows
        const int r = row + i * 32;
        cp16(sbuf + ABYTES + (uint32_t)(r * (ASTRH * 2) + c16 * 16),
             g_Wh + (bn + r) * D_MODEL + kt * BKH + c16 * 8);
    }
}

__device__ __forceinline__ uint32_t lds_h2(const __half* p) {
    return *(const uint32_t*)p;
}

__global__ void __launch_bounds__(256, 2)
gemm_kernel(float* __restrict__ C) {
    extern __shared__ __half smem[];
    const uint32_t sb = smem_u32(smem);

    const int tid  = threadIdx.x;
    const int wid  = tid >> 5;
    const int lane = tid & 31;
    const int gid  = lane >> 2;
    const int tig  = lane & 3;

    const size_t bm = (size_t)blockIdx.y * BM;
    const size_t bn = (size_t)blockIdx.x * BN;

    float acc[16][4];
    #pragma unroll
    for (int nt = 0; nt < 16; ++nt)
        #pragma unroll
        for (int k = 0; k < 4; ++k) acc[nt][k] = 0.f;

    stage_chunk(sb, 0, bm, bn, tid); CP_COMMIT();
    stage_chunk(sb + BUFB, 1, bm, bn, tid); CP_COMMIT();

    const int rbase = wid * 16 + gid;       // warp owns rows [wid*16, wid*16+16)
    for (int kt = 0; kt < NCHUNK; ++kt) {
        if (kt < NCHUNK - 1) { CP_WAIT(1); } else { CP_WAIT(0); }
        __syncthreads();

        if (kt + 2 < NCHUNK) {
            stage_chunk(sb + ((kt + 2) % 3) * BUFB, kt + 2, bm, bn, tid);
            CP_COMMIT();
        }

        const __half* As = smem + ((size_t)(kt % 3) * BUFB) / 2;
        const __half* Bs = As + ABYTES / 2;

        #pragma unroll
        for (int ks = 0; ks < 4; ++ks) {
            const int kc = ks * 16 + tig * 2;
            uint32_t a[4];
            a[0] = lds_h2(As + rbase * ASTRH + kc);
            a[1] = lds_h2(As + (rbase + 8) * ASTRH + kc);
            a[2] = lds_h2(As + rbase * ASTRH + kc + 8);
            a[3] = lds_h2(As + (rbase + 8) * ASTRH + kc + 8);
            #pragma unroll
            for (int nt = 0; nt < 16; ++nt) {
                const int n = nt * 8 + gid;
                const uint32_t b0 = lds_h2(Bs + n * ASTRH + kc);
                const uint32_t b1 = lds_h2(Bs + n * ASTRH + kc + 8);
                MMA_F16(acc[nt], a[0], a[1], a[2], a[3], b0, b1);
            }
        }
    }

    // ---- Epilogue: accs -> smem (row-major), lse per row, coalesced STG.
    __syncthreads();
    float* S = (float*)smem;                 // [128][ESTR], 67584 B
    #pragma unroll
    for (int h = 0; h < 2; ++h) {
        const int rl = wid * 16 + h * 8 + gid;
        #pragma unroll
        for (int nt = 0; nt < 16; ++nt)
            *(float2*)(S + rl * ESTR + nt * 8 + tig * 2) =
                make_float2(acc[nt][2 * h], acc[nt][2 * h + 1]);
    }
    __syncthreads();

    // Per-row lse partial: 2 threads per row (64 cols each), shfl-merge.
    {
        const int rl   = tid >> 1;
        const int half = tid & 1;
        const float* row = S + rl * ESTR + half * 64;
        float m = -1e30f;
        #pragma unroll
        for (int c = 0; c < 64; c += 4) {
            const float4 v = *(const float4*)(row + c);
            m = fmaxf(m, fmaxf(fmaxf(v.x, v.y), fmaxf(v.z, v.w)));
        }
        float s = 0.f;
        #pragma unroll
        for (int c = 0; c < 64; c += 4) {
            const float4 v = *(const float4*)(row + c);
            s += __expf(v.x - m) + __expf(v.y - m)
               + __expf(v.z - m) + __expf(v.w - m);
        }
        const float om = __shfl_xor_sync(0xFFFFFFFFu, m, 1);
        const float os = __shfl_xor_sync(0xFFFFFFFFu, s, 1);
        const float nm = fmaxf(m, om);
        s = s * __expf(m - nm) + os * __expf(om - nm);
        if (half == 0) {
            g_pmax[(bm + rl) * NTILES_N + blockIdx.x] = nm;
            g_psum[(bm + rl) * NTILES_N + blockIdx.x] = s;
        }
    }

    // Coalesced C store: warp covers 32 consecutive cols of one row per instr.
    {
        const int col = tid & 127;
        const int rh  = tid >> 7;            // 0 or 1
        #pragma unroll 8
        for (int it = 0; it < 64; ++it) {
            const int rl = it * 2 + rh;
            C[(bm + rl) * (size_t)VOCAB + bn + col] = S[rl * ESTR + col];
        }
    }
}

// ---------------------------------------------------------------------------
// 3) Combine partials -> per-row NLL, fused deterministic final reduction
// ---------------------------------------------------------------------------
__global__ void combine_loss_kernel(const float* __restrict__ scores,
                                    const int* __restrict__ labels,
                                    float* __restrict__ loss_out) {
    const int row = blockIdx.x;
    const int tid = threadIdx.x;
    __shared__ float red[256];
    __shared__ float red2[256];
    __shared__ unsigned last;

    float pm = -1e30f;
    if (tid < NTILES_N) pm = g_pmax[(size_t)row * NTILES_N + tid];
    red[tid] = pm; __syncthreads();
    #pragma unroll
    for (int s = 128; s > 0; s >>= 1) {
        if (tid < s) red[tid] = fmaxf(red[tid], red[tid + s]);
        __syncthreads();
    }
    const float M = red[0];
    __syncthreads();

    float ps = 0.f;
    if (tid < NTILES_N)
        ps = g_psum[(size_t)row * NTILES_N + tid] * __expf(pm - M);
    red[tid] = ps; __syncthreads();
    #pragma unroll
    for (int s = 128; s > 0; s >>= 1) {
        if (tid < s) red[tid] += red[tid + s];
        __syncthreads();
    }

    if (tid == 0) {
        const int l = labels[row];
        if (l != -100) {
            const int sl = (l >= 0 && l < VOCAB) ? l : 0;
            g_nll[row] = logf(red[0]) + M - scores[(size_t)row * VOCAB + sl];
            g_cnt[row] = 1.f;
        } else {
            g_nll[row] = 0.f;
            g_cnt[row] = 0.f;
        }
        __threadfence();
        const unsigned old = atomicAdd(&g_done, 1u);
        last = (old == NTOK - 1) ? 1u : 0u;
    }
    __syncthreads();

    if (last) {
        __threadfence();
        float s = 0.f, c = 0.f;
        for (int i = tid; i < NTOK; i += 256) { s += g_nll[i]; c += g_cnt[i]; }
        red[tid] = s; red2[tid] = c; __syncthreads();
        #pragma unroll
        for (int st = 128; st > 0; st >>= 1) {
            if (tid < st) { red[tid] += red[tid + st]; red2[tid] += red2[tid + st]; }
            __syncthreads();
        }
        if (tid == 0) {
            if (loss_out) loss_out[0] = red[0] / fmaxf(red2[0], 1.f);
            g_done = 0;
        }
    }
}

// ---------------------------------------------------------------------------
extern "C" void kernel_launch(void* const* d_in, const int* in_sizes, int n_in,
                              void* d_out, int out_size) {
    const float* hidden = (const float*)d_in[0];
    const int*   labels = (const int*)d_in[1];
    const float* lnw    = (const float*)d_in[2];
    const float* W      = (const float*)d_in[3];

    float* out = (float*)d_out;
    long long extra = (long long)out_size - (long long)NTOK * (long long)VOCAB;
    if (extra < 0) extra = 0;
    float* scores   = out + extra;
    float* loss_ptr = (extra >= 1) ? out : nullptr;

    static int smem_set = 0;
    if (!smem_set) {
        cudaFuncSetAttribute(gemm_kernel,
                             cudaFuncAttributeMaxDynamicSharedMemorySize, SMEM_TOTAL);
        smem_set = 1;
    }

    prep_kernel<<<NTOK + WCVT_BLOCKS, 256>>>(hidden, lnw, W);
    gemm_kernel<<<dim3(NTILES_N, NTOK / BM), 256, SMEM_TOTAL>>>(scores);
    combine_loss_kernel<<<NTOK, 256>>>(scores, labels, loss_ptr);
}